// round 7
// baseline (speedup 1.0000x reference)
#include <cuda_runtime.h>
#include <cstdint>

// ---------------------------------------------------------------------------
// SimpleLSTM on GB300 (sm_103a) — round 7: 4-CTA groups, full dot products
// per thread (no cross-warp reduction), L2 exchange + release/acquire flags.
//
//   kernel 1 (table_kernel): token table T[v][g] = E[v] . W_x^T + b for the
//       768 LIVE gate rows (F, O, Htmp; I gate is dead). Block (0,0) zeroes
//       the per-CTA flags. f32x2 inner product.
//   kernel 2 (lstm_kernel): 128 persistent CTAs = 32 groups x 4 col-tiles.
//       Group g owns batch rows 4g..4g+3; rank p owns hidden cols 64p..64p+63
//       and its 192KB W_h slice in SMEM. Thread (r, j) computes the full
//       256-k dot products for its 3 gates — no partial reduction. H is
//       exchanged via a global double buffer (st.cg / ld.cg); warp p<4 waits
//       on producer p's monotonic flag (st.release / ld.acquire). Self slice
//       comes from locally staged SMEM.
// ---------------------------------------------------------------------------

#define NB    128
#define LSEQ  2048
#define HDIM  256
#define EMB   256
#define VOC   32000
#define G3    768
#define NT    256

__device__ float    g_T[VOC * G3];          // token-gate table (~98.3 MB)
__device__ float    g_Hbuf[2][NB * HDIM];   // H double buffer
__device__ unsigned g_flags[128 * 64];      // per-CTA step flags, 256B stride

// ---------------------------------------------------------------------------
// helpers
// ---------------------------------------------------------------------------
__device__ __forceinline__ unsigned long long ffma2(unsigned long long a,
                                                    unsigned long long b,
                                                    unsigned long long c)
{
    unsigned long long d;
    asm("fma.rn.f32x2 %0, %1, %2, %3;" : "=l"(d) : "l"(a), "l"(b), "l"(c));
    return d;
}

__device__ __forceinline__ unsigned long long packf2(float lo, float hi)
{
    unsigned long long v;
    asm("mov.b64 %0, {%1, %2};" : "=l"(v) : "f"(lo), "f"(hi));
    return v;
}

__device__ __forceinline__ float f2sum(unsigned long long v)
{
    float2 f;
    asm("mov.b64 {%0, %1}, %2;" : "=f"(f.x), "=f"(f.y) : "l"(v));
    return f.x + f.y;
}

__device__ __forceinline__ unsigned ld_acq(const unsigned* p)
{
    unsigned v;
    asm volatile("ld.acquire.gpu.u32 %0, [%1];" : "=r"(v) : "l"(p) : "memory");
    return v;
}

__device__ __forceinline__ void st_rel(unsigned* p, unsigned v)
{
    asm volatile("st.release.gpu.u32 [%0], %1;" :: "l"(p), "r"(v) : "memory");
}

__device__ __forceinline__ float sig_fast(float x)
{
    return __fdividef(1.0f, 1.0f + __expf(-x));
}

__device__ __forceinline__ float tanh_fast(float x)
{
    return __fdividef(2.0f, 1.0f + __expf(-2.0f * x)) - 1.0f;
}

// ---------------------------------------------------------------------------
// Kernel 1: token table GEMM (M=32000, N=768 live gates, K=256)
// ---------------------------------------------------------------------------
__global__ void table_kernel(const float* __restrict__ E,
                             const float* __restrict__ Ww,
                             const float* __restrict__ Wb)
{
    __shared__ float Esm[32][68];
    __shared__ float Wsm[32][68];

    const int tid = threadIdx.x;
    const int v0  = blockIdx.x * 64;
    const int g0  = blockIdx.y * 64;

    if (blockIdx.x == 0 && blockIdx.y == 0) {
        for (int i = tid; i < 128 * 64; i += 256) g_flags[i] = 0u;
    }

    const int tx = tid & 15;
    const int ty = tid >> 4;

    unsigned long long acc2[4][2];
#pragma unroll
    for (int i = 0; i < 4; i++) { acc2[i][0] = 0ull; acc2[i][1] = 0ull; }

    for (int kb = 0; kb < 8; kb++) {
        for (int i = tid; i < 64 * 32; i += 256) {
            int row = i >> 5, kk = i & 31;
            Esm[kk][row] = E[(v0 + row) * EMB + kb * 32 + kk];
            int gg   = g0 + row;
            int gate = gg >> 8, jj = gg & 255;
            int grow = (gate == 0 ? 0 : (gate == 1 ? 512 : 768)) + jj;
            Wsm[kk][row] = Ww[grow * 512 + 256 + kb * 32 + kk];
        }
        __syncthreads();
#pragma unroll
        for (int kk = 0; kk < 32; kk++) {
            float4 a4 = *(const float4*)&Esm[kk][ty * 4];
            float4 b4 = *(const float4*)&Wsm[kk][tx * 4];
            unsigned long long blo = packf2(b4.x, b4.y);
            unsigned long long bhi = packf2(b4.z, b4.w);
            float av[4] = {a4.x, a4.y, a4.z, a4.w};
#pragma unroll
            for (int i = 0; i < 4; i++) {
                unsigned long long aa = packf2(av[i], av[i]);
                acc2[i][0] = ffma2(aa, blo, acc2[i][0]);
                acc2[i][1] = ffma2(aa, bhi, acc2[i][1]);
            }
        }
        __syncthreads();
    }

#pragma unroll
    for (int i = 0; i < 4; i++) {
        int v = v0 + ty * 4 + i;
#pragma unroll
        for (int jp = 0; jp < 2; jp++) {
            float2 f;
            asm("mov.b64 {%0, %1}, %2;" : "=f"(f.x), "=f"(f.y) : "l"(acc2[i][jp]));
            float fv[2] = {f.x, f.y};
#pragma unroll
            for (int s = 0; s < 2; s++) {
                int g    = g0 + tx * 4 + jp * 2 + s;
                int gate = g >> 8, jj = g & 255;
                int grow = (gate == 0 ? 0 : (gate == 1 ? 512 : 768)) + jj;
                g_T[v * G3 + g] = fv[s] + Wb[grow];
            }
        }
    }
}

// ---------------------------------------------------------------------------
// Kernel 2: persistent recurrence, 4-CTA groups, no cross-warp reduction.
// ---------------------------------------------------------------------------

// dynamic SMEM layout (bytes)
#define SM_W     0         // float4 Wsm[(k4*3+gate)*64 + j]  : 196608
#define SM_H     196608    // float4 Hsm[r*64 + k4]            : 4096
#define SM_C     200704    // float  Csm[256]                  : 1024
#define SM_HS    201728    // float  Hstage[256]               : 1024
#define SM_TOK   202752    // int    tokb[2][4]                : 64
#define SMEM_TOTAL 202816

__global__ void __launch_bounds__(NT, 1)
lstm_kernel(const void* __restrict__ Xraw,
            const float* __restrict__ Ww,
            float* __restrict__ out)
{
    extern __shared__ char smem[];
    float4*           Wsm4    = (float4*)(smem + SM_W);
    const ulonglong2* Wsm     = (const ulonglong2*)(smem + SM_W);
    float4*           Hsm4    = (float4*)(smem + SM_H);
    const ulonglong2* Hsm     = (const ulonglong2*)(smem + SM_H);
    float*            Csm     = (float*)(smem + SM_C);
    float*            Hstage  = (float*)(smem + SM_HS);
    const float4*     Hstage4 = (const float4*)(smem + SM_HS);
    int*              tokb    = (int*)(smem + SM_TOK);

    const int tid  = threadIdx.x;
    const int bt   = blockIdx.x >> 2;   // batch group 0..31
    const int ct   = blockIdx.x & 3;    // col tile 0..3
    const int rb   = bt * 4;            // first batch row
    const int j0   = ct * 64;           // first hidden col

    const int warp = tid >> 5;
    const int lane = tid & 31;
    const int er   = tid >> 6;          // output row 0..3 (uniform per warp)
    const int ej   = tid & 63;          // output col 0..63

    unsigned* myflag = &g_flags[blockIdx.x * 64];

    // --- int64 vs int32 token buffer detection ----------------------------
    const int* Xi = (const int*)Xraw;
    bool is64 = true;
#pragma unroll
    for (int i = 0; i < 16; i++)
        if (Xi[2 * i + 1] != 0) is64 = false;
    const long long* Xl = (const long long*)Xraw;

    // --- load W slice: Wsm[(k4*3+gate)*64 + j], 12288 float4 ---------------
    for (int i = tid; i < 12288; i += NT) {
        int k4   = i / 192;
        int rem  = i - k4 * 192;
        int gate = rem >> 6, j = rem & 63;
        int grow = (gate == 0 ? 0 : (gate == 1 ? 512 : 768)) + j0 + j;
        Wsm4[(k4 * 3 + gate) * 64 + j] = *(const float4*)(Ww + grow * 512 + k4 * 4);
    }
    Csm[tid] = 0.0f;
    for (int i = tid; i < 256; i += NT)           // Hsm zero (t=0)
        Hsm4[i] = make_float4(0.f, 0.f, 0.f, 0.f);
    if (tid < 4)
        tokb[tid] = is64 ? (int)Xl[(rb + tid) * LSEQ] : Xi[(rb + tid) * LSEQ];
    __syncthreads();

    // fill mapping for warps 0..3 (producer p = warp):
    //   element i in 0..63: r = i>>4, kk = i&15; k4 = p*16 + kk
    const int fr0 = lane >> 4,        fk0 = lane & 15;
    const int fr1 = (lane + 32) >> 4, fk1 = lane & 15;

    for (int t = 0; t < LSEQ; t++) {
        const int cur = t & 1, nxt = cur ^ 1;

        // ---- Gx prefetch (token-determined; overlaps wait/fill) ------------
        const float* Tr = g_T + (long long)tokb[cur * 4 + er] * G3 + j0 + ej;
        float gxF = __ldg(Tr);
        float gxO = __ldg(Tr + 256);
        float gxH = __ldg(Tr + 512);

        if (tid < 4 && t + 1 < LSEQ)
            tokb[nxt * 4 + tid] = is64 ? (int)Xl[(rb + tid) * LSEQ + t + 1]
                                       : Xi[(rb + tid) * LSEQ + t + 1];

        // ---- fill Hsm: warp p < 4 handles producer rank p ------------------
        if (t > 0 && warp < 4) {
            const int p = warp;
            if (p == ct) {
                // self slice staged locally last step (ordered by sync 2)
                Hsm4[fr0 * 64 + p * 16 + fk0] = Hstage4[fr0 * 16 + fk0];
                Hsm4[fr1 * 64 + p * 16 + fk1] = Hstage4[fr1 * 16 + fk1];
            } else {
                const unsigned* pf = &g_flags[(bt * 4 + p) * 64];
                unsigned target = (unsigned)t;
                while (ld_acq(pf) < target) { }
                const float* hb = g_Hbuf[cur];
                float4 v0 = __ldcg((const float4*)(hb + (rb + fr0) * HDIM + p * 64 + fk0 * 4));
                float4 v1 = __ldcg((const float4*)(hb + (rb + fr1) * HDIM + p * 64 + fk1 * 4));
                Hsm4[fr0 * 64 + p * 16 + fk0] = v0;
                Hsm4[fr1 * 64 + p * 16 + fk1] = v1;
            }
        }
        __syncthreads();   // (1) Hsm complete

        // ---- k-loop: full 256-k dot products, 3 gates, 1 output/thread -----
        unsigned long long aF0 = 0ull, aF1 = 0ull;
        unsigned long long aO0 = 0ull, aO1 = 0ull;
        unsigned long long aH0 = 0ull, aH1 = 0ull;

        const ulonglong2* Hrow = Hsm + er * 64;
#pragma unroll 8
        for (int k4 = 0; k4 < 64; k4++) {
            ulonglong2 hv = Hrow[k4];
            ulonglong2 wF = Wsm[(k4 * 3 + 0) * 64 + ej];
            ulonglong2 wO = Wsm[(k4 * 3 + 1) * 64 + ej];
            ulonglong2 wH = Wsm[(k4 * 3 + 2) * 64 + ej];
            aF0 = ffma2(wF.x, hv.x, aF0);
            aF1 = ffma2(wF.y, hv.y, aF1);
            aO0 = ffma2(wO.x, hv.x, aO0);
            aO1 = ffma2(wO.y, hv.y, aO1);
            aH0 = ffma2(wH.x, hv.x, aH0);
            aH1 = ffma2(wH.y, hv.y, aH1);
        }

        // ---- epilogue: gates, C, H_new (self-contained per thread) ---------
        {
            float gF = gxF + f2sum(aF0) + f2sum(aF1);
            float gO = gxO + f2sum(aO0) + f2sum(aO1);
            float gH = gxH + f2sum(aH0) + f2sum(aH1);
            float F  = sig_fast(gF);
            float O  = sig_fast(gO);
            float Ht = tanh_fast(gH);
            float c  = F * Csm[tid] + O * Ht;      // faithful: uses O, not I
            Csm[tid] = c;
            float hn = O * tanh_fast(c);
            Hstage[er * 64 + ej] = hn;
            __stcg(g_Hbuf[nxt] + (rb + er) * HDIM + j0 + ej, hn);
            if (t == LSEQ - 1)
                out[(rb + er) * HDIM + j0 + ej] = hn;
        }
        __syncthreads();   // (2) all stores issued; Hstage stable

        // ---- publish: monotonic flag, single writer, release ---------------
        if (tid == 0) st_rel(myflag, (unsigned)(t + 1));
    }
}

// ---------------------------------------------------------------------------
// launcher
// ---------------------------------------------------------------------------
extern "C" void kernel_launch(void* const* d_in, const int* in_sizes, int n_in,
                              void* d_out, int out_size)
{
    (void)in_sizes; (void)n_in; (void)out_size;
    const void*  X   = d_in[0];
    const float* E   = (const float*)d_in[1];
    const float* Ww  = (const float*)d_in[2];
    const float* Wb  = (const float*)d_in[3];
    float*       out = (float*)d_out;

    cudaFuncSetAttribute(lstm_kernel,
                         cudaFuncAttributeMaxDynamicSharedMemorySize,
                         SMEM_TOTAL);

    table_kernel<<<dim3(VOC / 64, G3 / 64), 256>>>(E, Ww, Wb);
    lstm_kernel<<<128, NT, SMEM_TOTAL>>>(X, Ww, out);
}

// round 8
// speedup vs baseline: 2.3249x; 2.3249x over previous
#include <cuda_runtime.h>
#include <cstdint>

// ---------------------------------------------------------------------------
// SimpleLSTM on GB300 (sm_103a) — round 8: round-5 structure (16 groups x 8
// CTAs, k-sliced warps, Gsm reduction) + TAGGED DATA EXCHANGE: the H values
// themselves carry a step tag (range offset), so consumers poll the data
// directly — no flags, no second L2 round trip.
//
//   Producer at step s stores  h + offs(s),  offs(s) = 4 + 8*((s>>1)&3).
//   h = tanh(.)*sig(.) is in (-1,1), so tagged ranges (3,5)/(11,13)/(19,21)/
//   (27,29) are disjoint from raw data, zeros, and (with the protocol's
//   skew bound) any stale generation — including a previous graph replay.
//   Each 16B chunk is one STG.128 / one L2 sector access: tear-free.
// ---------------------------------------------------------------------------

#define NB    128
#define LSEQ  2048
#define HDIM  256
#define EMB   256
#define VOC   32000
#define G3    768
#define NT    256

__device__ float g_T[VOC * G3];          // token-gate table (~98.3 MB)
__device__ float g_Hbuf[2][NB * HDIM];   // H double buffer (tagged values)

// ---------------------------------------------------------------------------
// helpers
// ---------------------------------------------------------------------------
__device__ __forceinline__ unsigned long long ffma2(unsigned long long a,
                                                    unsigned long long b,
                                                    unsigned long long c)
{
    unsigned long long d;
    asm("fma.rn.f32x2 %0, %1, %2, %3;" : "=l"(d) : "l"(a), "l"(b), "l"(c));
    return d;
}

__device__ __forceinline__ unsigned long long packf2(float lo, float hi)
{
    unsigned long long v;
    asm("mov.b64 %0, {%1, %2};" : "=l"(v) : "f"(lo), "f"(hi));
    return v;
}

__device__ __forceinline__ float f2sum(unsigned long long v)
{
    float2 f;
    asm("mov.b64 {%0, %1}, %2;" : "=f"(f.x), "=f"(f.y) : "l"(v));
    return f.x + f.y;
}

__device__ __forceinline__ float4 ldv4_volatile(const float* p)
{
    float4 v;
    asm volatile("ld.volatile.global.v4.f32 {%0, %1, %2, %3}, [%4];"
                 : "=f"(v.x), "=f"(v.y), "=f"(v.z), "=f"(v.w) : "l"(p)
                 : "memory");
    return v;
}

__device__ __forceinline__ float sig_fast(float x)
{
    return __fdividef(1.0f, 1.0f + __expf(-x));
}

__device__ __forceinline__ float tanh_fast(float x)
{
    return __fdividef(2.0f, 1.0f + __expf(-2.0f * x)) - 1.0f;
}

// ---------------------------------------------------------------------------
// Kernel 1: token table GEMM (M=32000, N=768 live gates, K=256)
// ---------------------------------------------------------------------------
__global__ void table_kernel(const float* __restrict__ E,
                             const float* __restrict__ Ww,
                             const float* __restrict__ Wb)
{
    __shared__ float Esm[32][68];
    __shared__ float Wsm[32][68];

    const int tid = threadIdx.x;
    const int v0  = blockIdx.x * 64;
    const int g0  = blockIdx.y * 64;

    const int tx = tid & 15;
    const int ty = tid >> 4;

    unsigned long long acc2[4][2];
#pragma unroll
    for (int i = 0; i < 4; i++) { acc2[i][0] = 0ull; acc2[i][1] = 0ull; }

    for (int kb = 0; kb < 8; kb++) {
        for (int i = tid; i < 64 * 32; i += 256) {
            int row = i >> 5, kk = i & 31;
            Esm[kk][row] = E[(v0 + row) * EMB + kb * 32 + kk];
            int gg   = g0 + row;
            int gate = gg >> 8, jj = gg & 255;
            int grow = (gate == 0 ? 0 : (gate == 1 ? 512 : 768)) + jj;
            Wsm[kk][row] = Ww[grow * 512 + 256 + kb * 32 + kk];
        }
        __syncthreads();
#pragma unroll
        for (int kk = 0; kk < 32; kk++) {
            float4 a4 = *(const float4*)&Esm[kk][ty * 4];
            float4 b4 = *(const float4*)&Wsm[kk][tx * 4];
            unsigned long long blo = packf2(b4.x, b4.y);
            unsigned long long bhi = packf2(b4.z, b4.w);
            float av[4] = {a4.x, a4.y, a4.z, a4.w};
#pragma unroll
            for (int i = 0; i < 4; i++) {
                unsigned long long aa = packf2(av[i], av[i]);
                acc2[i][0] = ffma2(aa, blo, acc2[i][0]);
                acc2[i][1] = ffma2(aa, bhi, acc2[i][1]);
            }
        }
        __syncthreads();
    }

#pragma unroll
    for (int i = 0; i < 4; i++) {
        int v = v0 + ty * 4 + i;
#pragma unroll
        for (int jp = 0; jp < 2; jp++) {
            float2 f;
            asm("mov.b64 {%0, %1}, %2;" : "=f"(f.x), "=f"(f.y) : "l"(acc2[i][jp]));
            float fv[2] = {f.x, f.y};
#pragma unroll
            for (int s = 0; s < 2; s++) {
                int g    = g0 + tx * 4 + jp * 2 + s;
                int gate = g >> 8, jj = g & 255;
                int grow = (gate == 0 ? 0 : (gate == 1 ? 512 : 768)) + jj;
                g_T[v * G3 + g] = fv[s] + Wb[grow];
            }
        }
    }
}

// ---------------------------------------------------------------------------
// Kernel 2: persistent recurrence, tagged-data exchange.
// ---------------------------------------------------------------------------

// dynamic SMEM layout (bytes)
#define SM_W     0         // float4 Wsm[(k4*3+gate)*32 + j]   : 98304
#define SM_H     98304     // float4 Hsm[r*64 + k4]             : 8192
#define SM_G     106496    // float  Gsm[((kq*3+g)*8+r)*32+j]   : 24576
#define SM_C     131072    // float  Csm[256]                   : 1024
#define SM_HS    132096    // float  Hstage[256]                : 1024
#define SM_TOK   133120    // int    tokb[2][8]                 : 64
#define SMEM_TOTAL 133184

__global__ void __launch_bounds__(NT, 1)
lstm_kernel(const void* __restrict__ Xraw,
            const float* __restrict__ Ww,
            float* __restrict__ out)
{
    extern __shared__ char smem[];
    float4*           Wsm4    = (float4*)(smem + SM_W);
    const ulonglong2* Wsm     = (const ulonglong2*)(smem + SM_W);
    float4*           Hsm4    = (float4*)(smem + SM_H);
    const ulonglong2* Hsm     = (const ulonglong2*)(smem + SM_H);
    float*            Gsm     = (float*)(smem + SM_G);
    float*            Csm     = (float*)(smem + SM_C);
    float*            Hstage  = (float*)(smem + SM_HS);
    const float4*     Hstage4 = (const float4*)(smem + SM_HS);
    int*              tokb    = (int*)(smem + SM_TOK);

    const int tid  = threadIdx.x;
    const int bt   = blockIdx.x >> 3;
    const int ct   = blockIdx.x & 7;
    const int rb   = bt * 8;
    const int j0   = ct * 32;

    const int kq   = tid >> 5;      // k-slice / producer CTA rank
    const int lane = tid & 31;

    // --- int64 vs int32 token buffer detection ----------------------------
    const int* Xi = (const int*)Xraw;
    bool is64 = true;
#pragma unroll
    for (int i = 0; i < 16; i++)
        if (Xi[2 * i + 1] != 0) is64 = false;
    const long long* Xl = (const long long*)Xraw;

    // --- load W slice: Wsm[(k4*3+gate)*32 + j] -----------------------------
    for (int i = tid; i < 96 * 64; i += NT) {
        int row = i >> 6, k4 = i & 63;
        int gate = row >> 5, j = row & 31;
        int grow = (gate == 0 ? 0 : (gate == 1 ? 512 : 768)) + j0 + j;
        Wsm4[(k4 * 3 + gate) * 32 + j] = *(const float4*)(Ww + grow * 512 + k4 * 4);
    }
    Csm[tid] = 0.0f;
    for (int i = tid; i < 512; i += NT)     // Hsm zero (used at t=0)
        Hsm4[i] = make_float4(0.f, 0.f, 0.f, 0.f);
    if (tid < 8)
        tokb[tid] = is64 ? (int)Xl[(rb + tid) * LSEQ] : Xi[(rb + tid) * LSEQ];
    __syncthreads();

    // per-lane H slice mapping
    const int r0 = lane >> 3,        q0 = lane & 7;
    const int r1 = (lane + 32) >> 3, q1 = lane & 7;

    for (int t = 0; t < LSEQ; t++) {
        const int cur = t & 1, nxt = cur ^ 1;

        // ---- Gx prefetch (token-determined; overlaps the wait) ------------
        const int er = kq, ej = lane;
        const float* Tr = g_T + (long long)tokb[cur * 8 + er] * G3 + j0 + ej;
        float gxF = __ldg(Tr);
        float gxO = __ldg(Tr + 256);
        float gxH = __ldg(Tr + 512);

        if (tid < 8 && t + 1 < LSEQ)
            tokb[nxt * 8 + tid] = is64 ? (int)Xl[(rb + tid) * LSEQ + t + 1]
                                       : Xi[(rb + tid) * LSEQ + t + 1];

        // ---- per-warp fill: poll tagged data from producer rank kq ---------
        if (t > 0) {
            if (kq == ct) {
                // self slice staged locally last step (ordered by sync B)
                Hsm4[r0 * 64 + kq * 8 + q0] = Hstage4[r0 * 8 + q0];
                Hsm4[r1 * 64 + kq * 8 + q1] = Hstage4[r1 * 8 + q1];
            } else {
                // expected tag for data written at step t-1
                const float cr = 4.0f + 8.0f * (float)(((t - 1) >> 1) & 3);
                const float* hb = g_Hbuf[cur];
                const float* p0 = hb + (rb + r0) * HDIM + kq * 32 + q0 * 4;
                const float* p1 = hb + (rb + r1) * HDIM + kq * 32 + q1 * 4;
                float4 v0, v1;
                bool d0 = false, d1 = false;
                do {
                    if (!d0) { v0 = ldv4_volatile(p0); d0 = fabsf(v0.x - cr) < 2.0f; }
                    if (!d1) { v1 = ldv4_volatile(p1); d1 = fabsf(v1.x - cr) < 2.0f; }
                } while (!(d0 && d1));
                v0.x -= cr; v0.y -= cr; v0.z -= cr; v0.w -= cr;
                v1.x -= cr; v1.y -= cr; v1.z -= cr; v1.w -= cr;
                Hsm4[r0 * 64 + kq * 8 + q0] = v0;
                Hsm4[r1 * 64 + kq * 8 + q1] = v1;
            }
            __syncwarp();
        }

        // ---- k-loop: this warp's k-slice, 3 gates, 8 rows ------------------
        unsigned long long aF[8], aO[8], aH[8];
#pragma unroll
        for (int r = 0; r < 8; r++) { aF[r] = 0ull; aO[r] = 0ull; aH[r] = 0ull; }

        const int kb = kq * 8;
#pragma unroll 4
        for (int u = 0; u < 8; u++) {
            const int k4 = kb + u;
            ulonglong2 wF = Wsm[(k4 * 3 + 0) * 32 + lane];
            ulonglong2 wO = Wsm[(k4 * 3 + 1) * 32 + lane];
            ulonglong2 wH = Wsm[(k4 * 3 + 2) * 32 + lane];
#pragma unroll
            for (int r = 0; r < 8; r++) {
                ulonglong2 hv = Hsm[r * 64 + k4];
                aF[r] = ffma2(wF.x, hv.x, aF[r]);
                aF[r] = ffma2(wF.y, hv.y, aF[r]);
                aO[r] = ffma2(wO.x, hv.x, aO[r]);
                aO[r] = ffma2(wO.y, hv.y, aO[r]);
                aH[r] = ffma2(wH.x, hv.x, aH[r]);
                aH[r] = ffma2(wH.y, hv.y, aH[r]);
            }
        }
#pragma unroll
        for (int r = 0; r < 8; r++) {
            Gsm[((kq * 3 + 0) * 8 + r) * 32 + lane] = f2sum(aF[r]);
            Gsm[((kq * 3 + 1) * 8 + r) * 32 + lane] = f2sum(aO[r]);
            Gsm[((kq * 3 + 2) * 8 + r) * 32 + lane] = f2sum(aH[r]);
        }
        __syncthreads();   // (A) join for the cross-warp reduction

        // ---- epilogue: reduce 8 partials, gates, C, H_new (tagged store) ---
        {
            const float cw = 4.0f + 8.0f * (float)((t >> 1) & 3);
            float gF = gxF, gO = gxO, gH = gxH;
#pragma unroll
            for (int q = 0; q < 8; q++) {
                gF += Gsm[((q * 3 + 0) * 8 + er) * 32 + ej];
                gO += Gsm[((q * 3 + 1) * 8 + er) * 32 + ej];
                gH += Gsm[((q * 3 + 2) * 8 + er) * 32 + ej];
            }
            float F  = sig_fast(gF);
            float O  = sig_fast(gO);
            float Ht = tanh_fast(gH);
            float c  = F * Csm[tid] + O * Ht;      // faithful: uses O, not I
            Csm[tid] = c;
            float hn = O * tanh_fast(c);
            Hstage[er * 32 + ej] = hn;                       // raw self-slice
            __stcg(g_Hbuf[nxt] + (rb + er) * HDIM + j0 + ej, hn + cw);
            if (t == LSEQ - 1)
                out[(rb + er) * HDIM + j0 + ej] = hn;
        }
        __syncthreads();   // (B) Gsm/Hstage stable before next step reuses them
    }
}

// ---------------------------------------------------------------------------
// launcher
// ---------------------------------------------------------------------------
extern "C" void kernel_launch(void* const* d_in, const int* in_sizes, int n_in,
                              void* d_out, int out_size)
{
    (void)in_sizes; (void)n_in; (void)out_size;
    const void*  X   = d_in[0];
    const float* E   = (const float*)d_in[1];
    const float* Ww  = (const float*)d_in[2];
    const float* Wb  = (const float*)d_in[3];
    float*       out = (float*)d_out;

    cudaFuncSetAttribute(lstm_kernel,
                         cudaFuncAttributeMaxDynamicSharedMemorySize,
                         SMEM_TOTAL);

    table_kernel<<<dim3(VOC / 64, G3 / 64), 256>>>(E, Ww, Wb);
    lstm_kernel<<<128, NT, SMEM_TOTAL>>>(X, Ww, out);
}

// round 10
// speedup vs baseline: 3.2509x; 1.3983x over previous
#include <cuda_runtime.h>
#include <cuda_bf16.h>
#include <cstdint>

// ---------------------------------------------------------------------------
// SimpleLSTM on GB300 (sm_103a harness targets plain sm_103 PTX) — round 10:
// warp-level HMMA (mma.sync m16n8k16 bf16) recurrence, W as register-resident
// A-fragments, tagged-data L2 exchange (round 8).
//
//   Per CTA per step:  G^T[96x8] = W[96x256] @ H^T[256x8]
//   - 6 MMA warps x m16 tile, full K per warp -> no cross-warp reduction.
//   - bf16 two-term split: W1H1 + W1H2 + W2H1 (fp32 accum; W2H2 ~1e-5 dropped)
//   - W fragments built once at init into registers (128 b32/thread).
//   - fill warps (8) poll tagged H slices from L2 and emit B-fragments in
//     native mma layout into SMEM (stride-34 slots: conflict-free LDS.32).
// ---------------------------------------------------------------------------

#define NB    128
#define LSEQ  2048
#define HDIM  256
#define EMB   256
#define VOC   32000
#define G3    768
#define NT    256

__device__ float g_T[VOC * G3];          // token-gate table (~98.3 MB)
__device__ float g_Hbuf[2][NB * HDIM];   // H double buffer (tagged values)

// ---------------------------------------------------------------------------
// helpers
// ---------------------------------------------------------------------------
__device__ __forceinline__ unsigned long long ffma2(unsigned long long a,
                                                    unsigned long long b,
                                                    unsigned long long c)
{
    unsigned long long d;
    asm("fma.rn.f32x2 %0, %1, %2, %3;" : "=l"(d) : "l"(a), "l"(b), "l"(c));
    return d;
}

__device__ __forceinline__ unsigned long long packf2(float lo, float hi)
{
    unsigned long long v;
    asm("mov.b64 %0, {%1, %2};" : "=l"(v) : "f"(lo), "f"(hi));
    return v;
}

__device__ __forceinline__ float4 ldv4_volatile(const float* p)
{
    float4 v;
    asm volatile("ld.volatile.global.v4.f32 {%0, %1, %2, %3}, [%4];"
                 : "=f"(v.x), "=f"(v.y), "=f"(v.z), "=f"(v.w) : "l"(p)
                 : "memory");
    return v;
}

__device__ __forceinline__ float sig_fast(float x)
{
    return __fdividef(1.0f, 1.0f + __expf(-x));
}

__device__ __forceinline__ float tanh_fast(float x)
{
    return __fdividef(2.0f, 1.0f + __expf(-2.0f * x)) - 1.0f;
}

// split a float2 (consecutive k pair) into bf16x2 hi and lo b32 values.
// low half of the b32 = first (even-k) element, matching mma operand layout.
__device__ __forceinline__ void split2(float2 f, uint32_t& hi, uint32_t& lo)
{
    __nv_bfloat16 h0 = __float2bfloat16_rn(f.x);
    __nv_bfloat16 h1 = __float2bfloat16_rn(f.y);
    __nv_bfloat16 l0 = __float2bfloat16_rn(f.x - __bfloat162float(h0));
    __nv_bfloat16 l1 = __float2bfloat16_rn(f.y - __bfloat162float(h1));
    __nv_bfloat162 ph = __halves2bfloat162(h0, h1);
    __nv_bfloat162 pl = __halves2bfloat162(l0, l1);
    hi = *(uint32_t*)&ph;
    lo = *(uint32_t*)&pl;
}

// split a float4 (4 consecutive k) into hi/lo uint2 (two bf16x2 pairs each)
__device__ __forceinline__ void split4(float4 v, uint2& hi, uint2& lo)
{
    split2(make_float2(v.x, v.y), hi.x, lo.x);
    split2(make_float2(v.z, v.w), hi.y, lo.y);
}

__device__ __forceinline__ void mma16816(float& c0, float& c1, float& c2, float& c3,
                                         uint32_t a0, uint32_t a1, uint32_t a2, uint32_t a3,
                                         uint32_t b0, uint32_t b1)
{
    asm volatile(
        "mma.sync.aligned.m16n8k16.row.col.f32.bf16.bf16.f32 "
        "{%0,%1,%2,%3}, {%4,%5,%6,%7}, {%8,%9}, {%0,%1,%2,%3};"
        : "+f"(c0), "+f"(c1), "+f"(c2), "+f"(c3)
        : "r"(a0), "r"(a1), "r"(a2), "r"(a3), "r"(b0), "r"(b1));
}

// ---------------------------------------------------------------------------
// Kernel 1: token table GEMM (M=32000, N=768 live gates, K=256)
// ---------------------------------------------------------------------------
__global__ void table_kernel(const float* __restrict__ E,
                             const float* __restrict__ Ww,
                             const float* __restrict__ Wb)
{
    __shared__ float Esm[32][68];
    __shared__ float Wsm[32][68];

    const int tid = threadIdx.x;
    const int v0  = blockIdx.x * 64;
    const int g0  = blockIdx.y * 64;

    const int tx = tid & 15;
    const int ty = tid >> 4;

    unsigned long long acc2[4][2];
#pragma unroll
    for (int i = 0; i < 4; i++) { acc2[i][0] = 0ull; acc2[i][1] = 0ull; }

    for (int kb = 0; kb < 8; kb++) {
        for (int i = tid; i < 64 * 32; i += 256) {
            int row = i >> 5, kk = i & 31;
            Esm[kk][row] = E[(v0 + row) * EMB + kb * 32 + kk];
            int gg   = g0 + row;
            int gate = gg >> 8, jj = gg & 255;
            int grow = (gate == 0 ? 0 : (gate == 1 ? 512 : 768)) + jj;
            Wsm[kk][row] = Ww[grow * 512 + 256 + kb * 32 + kk];
        }
        __syncthreads();
#pragma unroll
        for (int kk = 0; kk < 32; kk++) {
            float4 a4 = *(const float4*)&Esm[kk][ty * 4];
            float4 b4 = *(const float4*)&Wsm[kk][tx * 4];
            unsigned long long blo = packf2(b4.x, b4.y);
            unsigned long long bhi = packf2(b4.z, b4.w);
            float av[4] = {a4.x, a4.y, a4.z, a4.w};
#pragma unroll
            for (int i = 0; i < 4; i++) {
                unsigned long long aa = packf2(av[i], av[i]);
                acc2[i][0] = ffma2(aa, blo, acc2[i][0]);
                acc2[i][1] = ffma2(aa, bhi, acc2[i][1]);
            }
        }
        __syncthreads();
    }

#pragma unroll
    for (int i = 0; i < 4; i++) {
        int v = v0 + ty * 4 + i;
#pragma unroll
        for (int jp = 0; jp < 2; jp++) {
            float2 f;
            asm("mov.b64 {%0, %1}, %2;" : "=f"(f.x), "=f"(f.y) : "l"(acc2[i][jp]));
            float fv[2] = {f.x, f.y};
#pragma unroll
            for (int s = 0; s < 2; s++) {
                int g    = g0 + tx * 4 + jp * 2 + s;
                int gate = g >> 8, jj = g & 255;
                int grow = (gate == 0 ? 0 : (gate == 1 ? 512 : 768)) + jj;
                g_T[v * G3 + g] = fv[s] + Wb[grow];
            }
        }
    }
}

// ---------------------------------------------------------------------------
// Kernel 2: persistent recurrence, HMMA + tagged exchange.
// ---------------------------------------------------------------------------

#define SLOTW 34   // words per B-fragment slot (32 lanes + 2 pad)

__global__ void __launch_bounds__(NT, 1)
lstm_kernel(const void* __restrict__ Xraw,
            const float* __restrict__ Ww,
            float* __restrict__ out)
{
    // B fragments: slot = (split*16 + ktile)*2 + reg, word = slot*SLOTW + lane
    __shared__ uint32_t Bf[64 * SLOTW];      // 8704 B
    __shared__ float    Gsm2[96 * 9];        // G staging, stride 9 (bank-free)
    __shared__ float    Csm[256];
    __shared__ float    Hstage[256];
    __shared__ int      tokb[16];

    const int tid  = threadIdx.x;
    const int wid  = tid >> 5;
    const int lane = tid & 31;
    const int bt   = blockIdx.x >> 3;
    const int ct   = blockIdx.x & 7;
    const int rb   = bt * 8;
    const int j0   = ct * 32;

    const int gid = lane >> 2;      // mma group id
    const int tig = lane & 3;       // mma thread-in-group

    // --- int64 vs int32 token buffer detection ----------------------------
    const int* Xi = (const int*)Xraw;
    bool is64 = true;
#pragma unroll
    for (int i = 0; i < 16; i++)
        if (Xi[2 * i + 1] != 0) is64 = false;
    const long long* Xl = (const long long*)Xraw;

    // --- init: zero Bf, C; first tokens ------------------------------------
    for (int i = tid; i < 64 * SLOTW; i += NT) Bf[i] = 0u;
    Csm[tid] = 0.0f;
    if (tid < 8)
        tokb[tid] = is64 ? (int)Xl[(rb + tid) * LSEQ] : Xi[(rb + tid) * LSEQ];

    // --- build W A-fragments in registers (warps 0..5) ----------------------
    uint32_t A1[16][4], A2[16][4];
    if (wid < 6) {
        int m0 = wid * 16 + gid, m1 = m0 + 8;
        int ga = m0 >> 5, ja = m0 & 31;
        int gb = m1 >> 5, jb = m1 & 31;
        int grow0 = (ga == 0 ? 0 : (ga == 1 ? 512 : 768)) + j0 + ja;
        int grow1 = (gb == 0 ? 0 : (gb == 1 ? 512 : 768)) + j0 + jb;
#pragma unroll
        for (int kt = 0; kt < 16; kt++) {
            int k = kt * 16 + tig * 2;
            float2 f;
            f = __ldg((const float2*)(Ww + grow0 * 512 + k));
            split2(f, A1[kt][0], A2[kt][0]);
            f = __ldg((const float2*)(Ww + grow1 * 512 + k));
            split2(f, A1[kt][1], A2[kt][1]);
            f = __ldg((const float2*)(Ww + grow0 * 512 + k + 8));
            split2(f, A1[kt][2], A2[kt][2]);
            f = __ldg((const float2*)(Ww + grow1 * 512 + k + 8));
            split2(f, A1[kt][3], A2[kt][3]);
        }
    }
    __syncthreads();

    // --- fill mapping (all 8 warps; producer rank = wid) --------------------
    const int kq = wid;
    const int fq = lane & 7;            // k-quad within slice
    const int r0 = lane >> 3;           // batch rows 0..3 (v0)
    const int r1 = r0 + 4;              // batch rows 4..7 (v1)
    const int ktg  = kq * 2 + (fq >> 2);
    const int breg = (fq >> 1) & 1;
    const int btig = (fq & 1) * 2;
    const int slotHi = ktg * 2 + breg;             // split 1
    const int slotLo = (32 + ktg * 2) + breg;      // split 2 (+32 slots)
    const int offHi0 = slotHi * SLOTW + r0 * 4 + btig;
    const int offLo0 = slotLo * SLOTW + r0 * 4 + btig;
    const int offHi1 = slotHi * SLOTW + r1 * 4 + btig;
    const int offLo1 = slotLo * SLOTW + r1 * 4 + btig;

    const int er = tid >> 5, ej = lane;  // epilogue element (row, col)

    for (int t = 0; t < LSEQ; t++) {
        const int cur = t & 1, nxt = cur ^ 1;

        // ---- Gx prefetch (token-determined; overlaps the poll) ------------
        const float* Tr = g_T + (long long)tokb[cur * 8 + er] * G3 + j0 + ej;
        float gxF = __ldg(Tr);
        float gxO = __ldg(Tr + 256);
        float gxH = __ldg(Tr + 512);

        if (tid < 8 && t + 1 < LSEQ)
            tokb[nxt * 8 + tid] = is64 ? (int)Xl[(rb + tid) * LSEQ + t + 1]
                                       : Xi[(rb + tid) * LSEQ + t + 1];

        // ---- fill: poll tagged H slice, emit B-fragments -------------------
        if (t > 0) {
            float4 v0, v1;
            if (kq == ct) {
                v0 = ((const float4*)Hstage)[r0 * 8 + fq];
                v1 = ((const float4*)Hstage)[r1 * 8 + fq];
            } else {
                const float cr = 4.0f + 8.0f * (float)(((t - 1) >> 1) & 3);
                const float* hb = g_Hbuf[cur];
                const float* p0 = hb + (rb + r0) * HDIM + kq * 32 + fq * 4;
                const float* p1 = hb + (rb + r1) * HDIM + kq * 32 + fq * 4;
                bool d0 = false, d1 = false;
                do {
                    if (!d0) { v0 = ldv4_volatile(p0); d0 = fabsf(v0.x - cr) < 2.0f; }
                    if (!d1) { v1 = ldv4_volatile(p1); d1 = fabsf(v1.x - cr) < 2.0f; }
                } while (!(d0 && d1));
                v0.x -= cr; v0.y -= cr; v0.z -= cr; v0.w -= cr;
                v1.x -= cr; v1.y -= cr; v1.z -= cr; v1.w -= cr;
            }
            uint2 hi, lo;
            split4(v0, hi, lo);
            *(uint2*)&Bf[offHi0] = hi;
            *(uint2*)&Bf[offLo0] = lo;
            split4(v1, hi, lo);
            *(uint2*)&Bf[offHi1] = hi;
            *(uint2*)&Bf[offLo1] = lo;
        }
        __syncthreads();   // (1) B fragments ready

        // ---- HMMA: warps 0..5, 16 k-tiles x 3 split terms -------------------
        if (wid < 6) {
            float cA0 = 0.f, cA1 = 0.f, cA2 = 0.f, cA3 = 0.f;
            float cB0 = 0.f, cB1 = 0.f, cB2 = 0.f, cB3 = 0.f;
            float cC0 = 0.f, cC1 = 0.f, cC2 = 0.f, cC3 = 0.f;
#pragma unroll
            for (int kt = 0; kt < 16; kt++) {
                uint32_t b10 = Bf[(kt * 2 + 0) * SLOTW + lane];
                uint32_t b11 = Bf[(kt * 2 + 1) * SLOTW + lane];
                uint32_t b20 = Bf[(32 + kt * 2 + 0) * SLOTW + lane];
                uint32_t b21 = Bf[(32 + kt * 2 + 1) * SLOTW + lane];
                mma16816(cA0, cA1, cA2, cA3,
                         A1[kt][0], A1[kt][1], A1[kt][2], A1[kt][3], b10, b11);
                mma16816(cB0, cB1, cB2, cB3,
                         A1[kt][0], A1[kt][1], A1[kt][2], A1[kt][3], b20, b21);
                mma16816(cC0, cC1, cC2, cC3,
                         A2[kt][0], A2[kt][1], A2[kt][2], A2[kt][3], b10, b11);
            }
            int m0 = wid * 16 + gid, m1 = m0 + 8;
            Gsm2[m0 * 9 + tig * 2]     = cA0 + cB0 + cC0;
            Gsm2[m0 * 9 + tig * 2 + 1] = cA1 + cB1 + cC1;
            Gsm2[m1 * 9 + tig * 2]     = cA2 + cB2 + cC2;
            Gsm2[m1 * 9 + tig * 2 + 1] = cA3 + cB3 + cC3;
        }
        __syncthreads();   // (2) G ready

        // ---- epilogue: gates, C, H_new (tagged store) ------------------------
        {
            const float cw = 4.0f + 8.0f * (float)((t >> 1) & 3);
            float gF = gxF + Gsm2[ej * 9 + er];
            float gO = gxO + Gsm2[(32 + ej) * 9 + er];
            float gH = gxH + Gsm2[(64 + ej) * 9 + er];
            float F  = sig_fast(gF);
            float O  = sig_fast(gO);
            float Ht = tanh_fast(gH);
            float c  = F * Csm[tid] + O * Ht;      // faithful: uses O, not I
            Csm[tid] = c;
            float hn = O * tanh_fast(c);
            Hstage[er * 32 + ej] = hn;                       // raw self-slice
            __stcg(g_Hbuf[nxt] + (rb + er) * HDIM + j0 + ej, hn + cw);
            if (t == LSEQ - 1)
                out[(rb + er) * HDIM + j0 + ej] = hn;
        }
        __syncthreads();   // (3) Hstage stable; Bf free for next fill
    }
}

// ---------------------------------------------------------------------------
// launcher
// ---------------------------------------------------------------------------
extern "C" void kernel_launch(void* const* d_in, const int* in_sizes, int n_in,
                              void* d_out, int out_size)
{
    (void)in_sizes; (void)n_in; (void)out_size;
    const void*  X   = d_in[0];
    const float* E   = (const float*)d_in[1];
    const float* Ww  = (const float*)d_in[2];
    const float* Wb  = (const float*)d_in[3];
    float*       out = (float*)d_out;

    table_kernel<<<dim3(VOC / 64, G3 / 64), 256>>>(E, Ww, Wb);
    lstm_kernel<<<128, NT>>>(X, Ww, out);
}

// round 11
// speedup vs baseline: 3.5694x; 1.0980x over previous
#include <cuda_runtime.h>
#include <cuda_bf16.h>
#include <cstdint>

// ---------------------------------------------------------------------------
// SimpleLSTM on GB300 (plain sm_103 PTX) — round 11:
//   - lstm: HMMA recurrence (round 10) minus sync(3)/Hstage (self slice via
//     tagged L2 poll like remotes) with interleaved B-fragments (LDS.128).
//   - table: bf16-split HMMA GEMM; split_kernel pre-splits E / W_x once.
// ---------------------------------------------------------------------------

#define NB    128
#define LSEQ  2048
#define HDIM  256
#define EMB   256
#define VOC   32000
#define G3    768
#define NT    256

__device__ float    g_T[VOC * G3];          // token-gate table (~98.3 MB)
__device__ float    g_Hbuf[2][NB * HDIM];   // H double buffer (tagged values)
__device__ uint32_t g_EhG[VOC * 128];       // E hi split, bf16x2 words
__device__ uint32_t g_ElG[VOC * 128];       // E lo split
__device__ uint32_t g_WhG[G3 * 128];        // W_x hi split (live gate rows)
__device__ uint32_t g_WlG[G3 * 128];        // W_x lo split

// ---------------------------------------------------------------------------
// helpers
// ---------------------------------------------------------------------------
__device__ __forceinline__ float4 ldv4_volatile(const float* p)
{
    float4 v;
    asm volatile("ld.volatile.global.v4.f32 {%0, %1, %2, %3}, [%4];"
                 : "=f"(v.x), "=f"(v.y), "=f"(v.z), "=f"(v.w) : "l"(p)
                 : "memory");
    return v;
}

__device__ __forceinline__ float sig_fast(float x)
{
    return __fdividef(1.0f, 1.0f + __expf(-x));
}

__device__ __forceinline__ float tanh_fast(float x)
{
    return __fdividef(2.0f, 1.0f + __expf(-2.0f * x)) - 1.0f;
}

// split a float2 (consecutive k pair) into bf16x2 hi and lo b32 values.
__device__ __forceinline__ void split2(float2 f, uint32_t& hi, uint32_t& lo)
{
    __nv_bfloat16 h0 = __float2bfloat16_rn(f.x);
    __nv_bfloat16 h1 = __float2bfloat16_rn(f.y);
    __nv_bfloat16 l0 = __float2bfloat16_rn(f.x - __bfloat162float(h0));
    __nv_bfloat16 l1 = __float2bfloat16_rn(f.y - __bfloat162float(h1));
    __nv_bfloat162 ph = __halves2bfloat162(h0, h1);
    __nv_bfloat162 pl = __halves2bfloat162(l0, l1);
    hi = *(uint32_t*)&ph;
    lo = *(uint32_t*)&pl;
}

__device__ __forceinline__ void mma16816(float& c0, float& c1, float& c2, float& c3,
                                         uint32_t a0, uint32_t a1, uint32_t a2, uint32_t a3,
                                         uint32_t b0, uint32_t b1)
{
    asm volatile(
        "mma.sync.aligned.m16n8k16.row.col.f32.bf16.bf16.f32 "
        "{%0,%1,%2,%3}, {%4,%5,%6,%7}, {%8,%9}, {%0,%1,%2,%3};"
        : "+f"(c0), "+f"(c1), "+f"(c2), "+f"(c3)
        : "r"(a0), "r"(a1), "r"(a2), "r"(a3), "r"(b0), "r"(b1));
}

__device__ __forceinline__ int grow_of(int g)   // live-gate row -> W row
{
    int gate = g >> 8, jj = g & 255;
    return (gate == 0 ? 0 : (gate == 1 ? 512 : 768)) + jj;
}

// ---------------------------------------------------------------------------
// Kernel 0: split E and W_x (input half, live gate rows) into bf16 hi/lo.
// grid: 8192 x 256 threads, one float4 per thread (E: 2,048,000, W: 49,152).
// ---------------------------------------------------------------------------
__global__ void split_kernel(const float* __restrict__ E,
                             const float* __restrict__ Ww)
{
    int idx = blockIdx.x * 256 + threadIdx.x;
    uint32_t h0, l0, h1, l1;
    if (idx < VOC * 64) {
        int row = idx >> 6, f4 = idx & 63;
        float4 e = *(const float4*)(E + row * EMB + f4 * 4);
        split2(make_float2(e.x, e.y), h0, l0);
        split2(make_float2(e.z, e.w), h1, l1);
        *(uint2*)&g_EhG[row * 128 + f4 * 2] = make_uint2(h0, h1);
        *(uint2*)&g_ElG[row * 128 + f4 * 2] = make_uint2(l0, l1);
    } else {
        int widx = idx - VOC * 64;
        int row = widx >> 6, f4 = widx & 63;      // row = live gate idx 0..767
        int grow = grow_of(row);
        float4 w = *(const float4*)(Ww + grow * 512 + 256 + f4 * 4);
        split2(make_float2(w.x, w.y), h0, l0);
        split2(make_float2(w.z, w.w), h1, l1);
        *(uint2*)&g_WhG[row * 128 + f4 * 2] = make_uint2(h0, h1);
        *(uint2*)&g_WlG[row * 128 + f4 * 2] = make_uint2(l0, l1);
    }
}

// ---------------------------------------------------------------------------
// Kernel 1: token table GEMM via HMMA (M=32000, N=768, K=256), 64x64 tiles.
//   3-term bf16 split: EhWh + EhWl + ElWh. SMEM row stride 36 words
//   (conflict-free frag loads: addr mod 32 = 4*gid + tig).
// ---------------------------------------------------------------------------
__global__ void __launch_bounds__(256)
table_kernel(const float* __restrict__ Wb)
{
    __shared__ uint32_t Eh[64 * 36], El[64 * 36];
    __shared__ uint32_t Wh[64 * 36], Wl[64 * 36];

    const int tid  = threadIdx.x;
    const int v0   = blockIdx.x * 64;
    const int g0   = blockIdx.y * 64;
    const int wid  = tid >> 5, lane = tid & 31;
    const int gid  = lane >> 2, tig = lane & 3;
    const int m0   = (wid & 3) * 16;
    const int n0   = (wid >> 2) * 32;

    float acc[4][4];
#pragma unroll
    for (int i = 0; i < 4; i++)
#pragma unroll
        for (int j = 0; j < 4; j++) acc[i][j] = 0.0f;

    for (int c = 0; c < 4; c++) {          // K chunk of 64
        // load 4 tiles (Eh/El/Wh/Wl), each 64 rows x 8 uint4
#pragma unroll
        for (int it = 0; it < 8; it++) {
            int idx = tid + it * 256;       // 0..2047
            int buf = idx >> 9, rem = idx & 511;
            int row = rem >> 3, w4 = rem & 7;
            const uint32_t* src;
            uint32_t* dst;
            if (buf == 0)      { src = &g_EhG[(v0 + row) * 128]; dst = Eh; }
            else if (buf == 1) { src = &g_ElG[(v0 + row) * 128]; dst = El; }
            else if (buf == 2) { src = &g_WhG[(g0 + row) * 128]; dst = Wh; }
            else               { src = &g_WlG[(g0 + row) * 128]; dst = Wl; }
            uint4 v = *(const uint4*)(src + c * 32 + w4 * 4);
            *(uint4*)(dst + row * 36 + w4 * 4) = v;
        }
        __syncthreads();

#pragma unroll
        for (int ktL = 0; ktL < 4; ktL++) {
            int kw = ktL * 8 + tig;
            uint32_t ah0 = Eh[(m0 + gid) * 36 + kw];
            uint32_t ah1 = Eh[(m0 + gid + 8) * 36 + kw];
            uint32_t ah2 = Eh[(m0 + gid) * 36 + kw + 4];
            uint32_t ah3 = Eh[(m0 + gid + 8) * 36 + kw + 4];
            uint32_t al0 = El[(m0 + gid) * 36 + kw];
            uint32_t al1 = El[(m0 + gid + 8) * 36 + kw];
            uint32_t al2 = El[(m0 + gid) * 36 + kw + 4];
            uint32_t al3 = El[(m0 + gid + 8) * 36 + kw + 4];
#pragma unroll
            for (int nn = 0; nn < 4; nn++) {
                int wr = (n0 + nn * 8 + gid) * 36 + kw;
                uint32_t bh0 = Wh[wr], bh1 = Wh[wr + 4];
                uint32_t bl0 = Wl[wr], bl1 = Wl[wr + 4];
                mma16816(acc[nn][0], acc[nn][1], acc[nn][2], acc[nn][3],
                         ah0, ah1, ah2, ah3, bh0, bh1);
                mma16816(acc[nn][0], acc[nn][1], acc[nn][2], acc[nn][3],
                         ah0, ah1, ah2, ah3, bl0, bl1);
                mma16816(acc[nn][0], acc[nn][1], acc[nn][2], acc[nn][3],
                         al0, al1, al2, al3, bh0, bh1);
            }
        }
        __syncthreads();
    }

    // epilogue: add bias, store
#pragma unroll
    for (int nn = 0; nn < 4; nn++) {
        int g  = g0 + n0 + nn * 8 + tig * 2;
        float b0 = Wb[grow_of(g)];
        float b1 = Wb[grow_of(g + 1)];
        int vA = v0 + m0 + gid, vB = vA + 8;
        *(float2*)&g_T[vA * G3 + g] = make_float2(acc[nn][0] + b0, acc[nn][1] + b1);
        *(float2*)&g_T[vB * G3 + g] = make_float2(acc[nn][2] + b0, acc[nn][3] + b1);
    }
}

// ---------------------------------------------------------------------------
// Kernel 2: persistent recurrence, HMMA + tagged exchange (2 syncs/step).
// ---------------------------------------------------------------------------

#define KTW 132   // words per k-tile slot (128 + 4 pad)

__global__ void __launch_bounds__(NT, 1)
lstm_kernel(const void* __restrict__ Xraw,
            const float* __restrict__ Ww,
            float* __restrict__ out)
{
    // Bf word = kt*KTW + lane*4 + q, q = reg*2 + split
    __shared__ uint32_t Bf[16 * KTW];        // 8448 B
    __shared__ float    Gsm2[96 * 9];        // G staging, stride 9 (bank-free)
    __shared__ float    Csm[256];
    __shared__ int      tokb[16];

    const int tid  = threadIdx.x;
    const int wid  = tid >> 5;
    const int lane = tid & 31;
    const int bt   = blockIdx.x >> 3;
    const int ct   = blockIdx.x & 7;
    const int rb   = bt * 8;
    const int j0   = ct * 32;

    const int gid = lane >> 2;      // mma group id
    const int tig = lane & 3;       // mma thread-in-group

    // --- int64 vs int32 token buffer detection ----------------------------
    const int* Xi = (const int*)Xraw;
    bool is64 = true;
#pragma unroll
    for (int i = 0; i < 16; i++)
        if (Xi[2 * i + 1] != 0) is64 = false;
    const long long* Xl = (const long long*)Xraw;

    // --- init: zero Bf, C; first tokens ------------------------------------
    for (int i = tid; i < 16 * KTW; i += NT) Bf[i] = 0u;
    Csm[tid] = 0.0f;
    if (tid < 8)
        tokb[tid] = is64 ? (int)Xl[(rb + tid) * LSEQ] : Xi[(rb + tid) * LSEQ];

    // --- build W A-fragments in registers (warps 0..5) ----------------------
    uint32_t A1[16][4], A2[16][4];
    if (wid < 6) {
        int m0 = wid * 16 + gid, m1 = m0 + 8;
        int grow0 = grow_of((m0 >> 5) * 256 + (m0 & 31)) + j0;   // careful below
        // grow mapping: m = gate*32 + j  ->  W row = grow_of(gate*256 + ...) —
        // compute directly instead:
        int ga = m0 >> 5, ja = m0 & 31;
        int gb = m1 >> 5, jb = m1 & 31;
        grow0     = (ga == 0 ? 0 : (ga == 1 ? 512 : 768)) + j0 + ja;
        int grow1 = (gb == 0 ? 0 : (gb == 1 ? 512 : 768)) + j0 + jb;
#pragma unroll
        for (int kt = 0; kt < 16; kt++) {
            int k = kt * 16 + tig * 2;
            float2 f;
            f = __ldg((const float2*)(Ww + grow0 * 512 + k));
            split2(f, A1[kt][0], A2[kt][0]);
            f = __ldg((const float2*)(Ww + grow1 * 512 + k));
            split2(f, A1[kt][1], A2[kt][1]);
            f = __ldg((const float2*)(Ww + grow0 * 512 + k + 8));
            split2(f, A1[kt][2], A2[kt][2]);
            f = __ldg((const float2*)(Ww + grow1 * 512 + k + 8));
            split2(f, A1[kt][3], A2[kt][3]);
        }
    }
    __syncthreads();

    // --- fill mapping (all 8 warps; producer rank = wid) --------------------
    const int kq = wid;
    const int fq = lane & 7;            // k-quad within slice
    const int r0 = lane >> 3;           // batch rows 0..3 (v0)
    const int r1 = r0 + 4;              // batch rows 4..7 (v1)
    const int fkt  = kq * 2 + (fq >> 2);
    const int freg = (fq >> 1) & 1;
    const int ftig = (fq & 1) * 2;
    uint2* B2 = (uint2*)Bf;
    const int u0a = fkt * (KTW / 2) + (r0 * 4 + ftig) * 2 + freg;      // pair0 of v0
    const int u0b = fkt * (KTW / 2) + (r0 * 4 + ftig + 1) * 2 + freg;  // pair1 of v0
    const int u1a = fkt * (KTW / 2) + (r1 * 4 + ftig) * 2 + freg;
    const int u1b = fkt * (KTW / 2) + (r1 * 4 + ftig + 1) * 2 + freg;

    const int er = tid >> 5, ej = lane;  // epilogue element (row, col)

    for (int t = 0; t < LSEQ; t++) {
        const int cur = t & 1, nxt = cur ^ 1;

        // ---- Gx prefetch (token-determined; overlaps the poll) ------------
        const float* Tr = g_T + (long long)tokb[cur * 8 + er] * G3 + j0 + ej;
        float gxF = __ldg(Tr);
        float gxO = __ldg(Tr + 256);
        float gxH = __ldg(Tr + 512);

        if (tid < 8 && t + 1 < LSEQ)
            tokb[nxt * 8 + tid] = is64 ? (int)Xl[(rb + tid) * LSEQ + t + 1]
                                       : Xi[(rb + tid) * LSEQ + t + 1];

        // ---- fill: poll tagged H slice (self included), emit B fragments --
        if (t > 0) {
            const float cr = 4.0f + 8.0f * (float)(((t - 1) >> 1) & 3);
            const float* hb = g_Hbuf[cur];
            const float* p0 = hb + (rb + r0) * HDIM + kq * 32 + fq * 4;
            const float* p1 = hb + (rb + r1) * HDIM + kq * 32 + fq * 4;
            float4 v0, v1;
            bool d0 = false, d1 = false;
            do {
                if (!d0) { v0 = ldv4_volatile(p0); d0 = fabsf(v0.x - cr) < 2.0f; }
                if (!d1) { v1 = ldv4_volatile(p1); d1 = fabsf(v1.x - cr) < 2.0f; }
            } while (!(d0 && d1));
            v0.x -= cr; v0.y -= cr; v0.z -= cr; v0.w -= cr;
            v1.x -= cr; v1.y -= cr; v1.z -= cr; v1.w -= cr;
            uint32_t h0, l0, h1, l1;
            split2(make_float2(v0.x, v0.y), h0, l0);
            split2(make_float2(v0.z, v0.w), h1, l1);
            B2[u0a] = make_uint2(h0, l0);
            B2[u0b] = make_uint2(h1, l1);
            split2(make_float2(v1.x, v1.y), h0, l0);
            split2(make_float2(v1.z, v1.w), h1, l1);
            B2[u1a] = make_uint2(h0, l0);
            B2[u1b] = make_uint2(h1, l1);
        }
        __syncthreads();   // (1) B fragments ready

        // ---- HMMA: warps 0..5, 16 k-tiles x 3 split terms (LDS.128 B) ------
        if (wid < 6) {
            float cA0 = 0.f, cA1 = 0.f, cA2 = 0.f, cA3 = 0.f;
            float cB0 = 0.f, cB1 = 0.f, cB2 = 0.f, cB3 = 0.f;
            float cC0 = 0.f, cC1 = 0.f, cC2 = 0.f, cC3 = 0.f;
#pragma unroll
            for (int kt = 0; kt < 16; kt++) {
                uint4 b = *(const uint4*)&Bf[kt * KTW + lane * 4];
                // words: x=b1r0(hi), y=b2r0(lo), z=b1r1(hi), w=b2r1(lo)
                mma16816(cA0, cA1, cA2, cA3,
                         A1[kt][0], A1[kt][1], A1[kt][2], A1[kt][3], b.x, b.z);
                mma16816(cB0, cB1, cB2, cB3,
                         A1[kt][0], A1[kt][1], A1[kt][2], A1[kt][3], b.y, b.w);
                mma16816(cC0, cC1, cC2, cC3,
                         A2[kt][0], A2[kt][1], A2[kt][2], A2[kt][3], b.x, b.z);
            }
            int m0 = wid * 16 + gid, m1 = m0 + 8;
            Gsm2[m0 * 9 + tig * 2]     = cA0 + cB0 + cC0;
            Gsm2[m0 * 9 + tig * 2 + 1] = cA1 + cB1 + cC1;
            Gsm2[m1 * 9 + tig * 2]     = cA2 + cB2 + cC2;
            Gsm2[m1 * 9 + tig * 2 + 1] = cA3 + cB3 + cC3;
        }
        __syncthreads();   // (2) G ready

        // ---- epilogue: gates, C, H_new (tagged store) ------------------------
        {
            const float cw = 4.0f + 8.0f * (float)((t >> 1) & 3);
            float gF = gxF + Gsm2[ej * 9 + er];
            float gO = gxO + Gsm2[(32 + ej) * 9 + er];
            float gH = gxH + Gsm2[(64 + ej) * 9 + er];
            float F  = sig_fast(gF);
            float O  = sig_fast(gO);
            float Ht = tanh_fast(gH);
            float c  = F * Csm[tid] + O * Ht;      // faithful: uses O, not I
            Csm[tid] = c;
            float hn = O * tanh_fast(c);
            __stcg(g_Hbuf[nxt] + (rb + er) * HDIM + j0 + ej, hn + cw);
            if (t == LSEQ - 1)
                out[(rb + er) * HDIM + j0 + ej] = hn;
        }
        // no third sync: Bf next write fenced by (2); Gsm2 next write by (1)
    }
}

// ---------------------------------------------------------------------------
// launcher
// ---------------------------------------------------------------------------
extern "C" void kernel_launch(void* const* d_in, const int* in_sizes, int n_in,
                              void* d_out, int out_size)
{
    (void)in_sizes; (void)n_in; (void)out_size;
    const void*  X   = d_in[0];
    const float* E   = (const float*)d_in[1];
    const float* Ww  = (const float*)d_in[2];
    const float* Wb  = (const float*)d_in[3];
    float*       out = (float*)d_out;

    split_kernel<<<8192, 256>>>(E, Ww);
    table_kernel<<<dim3(VOC / 64, G3 / 64), 256>>>(Wb);
    lstm_kernel<<<128, NT>>>(X, Ww, out);
}